// round 6
// baseline (speedup 1.0000x reference)
#include <cuda_runtime.h>
#include <math.h>
#include <stdint.h>

#define T_TOK 8192
#define D_DIM 1024
#define F_DIM 4096
#define E_EXP 8
#define NSLOT (2 * T_TOK)

// ---------------- scratch (static device globals; no allocations) ----------
__device__ int    g_cnt[E_EXP];
__device__ int    g_off[E_EXP];
__device__ int    g_tok[E_EXP * T_TOK];
__device__ float  g_wt [E_EXP * T_TOK];

__device__ int8_t g_xa [(size_t)T_TOK * D_DIM];
__device__ int8_t g_xb [(size_t)T_TOK * D_DIM];
__device__ float  g_sx [T_TOK];
__device__ int8_t g_w1a[(size_t)E_EXP * F_DIM * D_DIM];
__device__ int8_t g_w1b[(size_t)E_EXP * F_DIM * D_DIM];
__device__ float  g_sw1[E_EXP * F_DIM];
__device__ int8_t g_w2a[(size_t)E_EXP * D_DIM * F_DIM];
__device__ int8_t g_w2b[(size_t)E_EXP * D_DIM * F_DIM];
__device__ float  g_sw2[E_EXP * D_DIM];
__device__ float  g_hf [(size_t)NSLOT * F_DIM];
__device__ int8_t g_ha [(size_t)NSLOT * F_DIM];
__device__ int8_t g_hb [(size_t)NSLOT * F_DIM];
__device__ float  g_sh [NSLOT];

// ---------------- PTX helpers (sm_80+ features only) ------------------------
__device__ __forceinline__ uint32_t smem_u32(const void* p) {
    uint32_t a;
    asm("{ .reg .u64 t; cvta.to.shared.u64 t, %1; cvt.u32.u64 %0, t; }" : "=r"(a) : "l"(p));
    return a;
}
#define CP16(dst, src) asm volatile("cp.async.cg.shared.global [%0], [%1], 16;" :: "r"(dst), "l"(src) : "memory")
#define CP_COMMIT()    asm volatile("cp.async.commit_group;" ::: "memory")
#define CP_WAIT(n)     asm volatile("cp.async.wait_group %0;" :: "n"(n) : "memory")
#define LDX4(r, a)                                                             \
    asm volatile("ldmatrix.sync.aligned.m8n8.x4.shared.b16 {%0,%1,%2,%3}, [%4];" \
        : "=r"((r)[0]), "=r"((r)[1]), "=r"((r)[2]), "=r"((r)[3]) : "r"(a))
#define IMMA(d, a, b0, b1)                                                     \
    asm volatile("mma.sync.aligned.m16n8k32.row.col.s32.s8.s8.s32 "            \
        "{%0,%1,%2,%3},{%4,%5,%6,%7},{%8,%9},{%0,%1,%2,%3};"                   \
        : "+r"((d)[0]), "+r"((d)[1]), "+r"((d)[2]), "+r"((d)[3])               \
        : "r"((a)[0]), "r"((a)[1]), "r"((a)[2]), "r"((a)[3]), "r"(b0), "r"(b1))

// SMEM header: toks @0 (512B), bias @512, s_m @1024, s_n @1536, wts @2048
// Stage (pitch 80B = 64 s8 + 16B pad): Aa @0, Ab @10240, Ba @20480, Bb @30720
#define SM_HDR  2560
#define STG_SZ  40960
#define NSTAGE  4
#define SMEM_DYN (SM_HDR + NSTAGE * STG_SZ)

// ---------------- init ------------------------------------------------------
__global__ void k_init(float4* __restrict__ out4) {
    int i = blockIdx.x * blockDim.x + threadIdx.x;
    if (i < E_EXP) g_cnt[i] = 0;
    const size_t n4 = (size_t)T_TOK * D_DIM / 4;
    float4 z = make_float4(0.f, 0.f, 0.f, 0.f);
    for (size_t j = i; j < n4; j += (size_t)gridDim.x * blockDim.x) out4[j] = z;
}

// ---------------- per-row 2-byte fixed-point quantization -------------------
// row = s*(a + b/256), s = absmax/127, a,b in s8. Exact rowmax per row.
__global__ __launch_bounds__(256) void k_qrows(const float* __restrict__ src,
                                               int8_t* __restrict__ da,
                                               int8_t* __restrict__ db,
                                               float* __restrict__ sc, int rowlen) {
    const int row = blockIdx.x, tid = threadIdx.x;
    const float* s = src + (size_t)row * rowlen;
    __shared__ float red[256];
    float mx = 0.f;
    for (int i = tid; i < rowlen; i += 256) mx = fmaxf(mx, fabsf(s[i]));
    red[tid] = mx; __syncthreads();
#pragma unroll
    for (int o = 128; o > 0; o >>= 1) {
        if (tid < o) red[tid] = fmaxf(red[tid], red[tid + o]);
        __syncthreads();
    }
    mx = red[0];
    const float scale = (mx > 1e-30f) ? mx / 127.f : 1.f;
    const float inv   = (mx > 1e-30f) ? 127.f / mx : 0.f;
    if (tid == 0) sc[row] = scale;
    int8_t* pa = da + (size_t)row * rowlen;
    int8_t* pb = db + (size_t)row * rowlen;
    for (int i = tid; i < rowlen; i += 256) {
        float u = s[i] * inv;
        float a = rintf(u);
        float b = fminf(rintf((u - a) * 256.f), 127.f);
        pa[i] = (int8_t)(int)a;
        pb[i] = (int8_t)(int)b;
    }
}

// ---------------- gating (validated) ----------------------------------------
__global__ void k_gate(const float* __restrict__ x, const float* __restrict__ gw,
                       float* __restrict__ probs_out) {
    int warp = (blockIdx.x * blockDim.x + threadIdx.x) >> 5;
    int lane = threadIdx.x & 31;
    if (warp >= T_TOK) return;
    const float* xr = x + (size_t)warp * D_DIM;
    float acc[E_EXP];
#pragma unroll
    for (int e = 0; e < E_EXP; e++) acc[e] = 0.f;
    for (int k = lane * 4; k < D_DIM; k += 128) {
        float4 xv = *(const float4*)(xr + k);
#pragma unroll
        for (int e = 0; e < E_EXP; e++) {
            float4 wv = *(const float4*)(gw + (size_t)e * D_DIM + k);
            acc[e] += xv.x * wv.x + xv.y * wv.y + xv.z * wv.z + xv.w * wv.w;
        }
    }
#pragma unroll
    for (int e = 0; e < E_EXP; e++)
#pragma unroll
        for (int o = 16; o > 0; o >>= 1) acc[e] += __shfl_xor_sync(0xffffffffu, acc[e], o);
    if (lane == 0) {
        float mx = acc[0];
#pragma unroll
        for (int e = 1; e < E_EXP; e++) mx = fmaxf(mx, acc[e]);
        float p[E_EXP], s = 0.f;
#pragma unroll
        for (int e = 0; e < E_EXP; e++) { p[e] = expf(acc[e] - mx); s += p[e]; }
        float inv = 1.f / s;
#pragma unroll
        for (int e = 0; e < E_EXP; e++) {
            p[e] *= inv;
            probs_out[(size_t)warp * E_EXP + e] = p[e];
        }
        int i0 = 0;
#pragma unroll
        for (int e = 1; e < E_EXP; e++) if (p[e] > p[i0]) i0 = e;
        int i1 = (i0 == 0) ? 1 : 0;
#pragma unroll
        for (int e = 0; e < E_EXP; e++) if (e != i0 && p[e] > p[i1]) i1 = e;
        float denom = p[i0] + p[i1] + 1e-9f;
        int s0 = atomicAdd(&g_cnt[i0], 1);
        g_tok[i0 * T_TOK + s0] = warp; g_wt[i0 * T_TOK + s0] = p[i0] / denom;
        int s1 = atomicAdd(&g_cnt[i1], 1);
        g_tok[i1 * T_TOK + s1] = warp; g_wt[i1 * T_TOK + s1] = p[i1] / denom;
    }
}
__global__ void k_prefix() {
    if (threadIdx.x == 0) {
        int run = 0;
#pragma unroll
        for (int e = 0; e < E_EXP; e++) { g_off[e] = run; run += g_cnt[e]; }
    }
}

// ---------------- GEMM core: 512 thr, block 128x128, warp 32x32, k-chunk 64 -
// out = sA*sB*(acc0 + acc1/256); acc0 += a*c; acc1 += a*d + b*c (bd dropped).
#define LDM_SETUP()                                                            \
    const int lane = tid & 31, wid = tid >> 5;                                 \
    const int wm = (wid & 3) * 32, wn = (wid >> 2) * 32;                       \
    uint32_t aav[2];                                                           \
    _Pragma("unroll") for (int mt = 0; mt < 2; ++mt)                           \
        aav[mt] = sb + SM_HDR +                                                \
            (wm + mt * 16 + (lane & 7) + ((lane >> 3) & 1) * 8) * 80 +         \
            ((lane >> 4) & 1) * 16;                                            \
    uint32_t bbv[2];                                                           \
    _Pragma("unroll") for (int g = 0; g < 2; ++g)                              \
        bbv[g] = sb + SM_HDR + 20480 +                                         \
            (wn + g * 16 + (lane & 7) + ((lane >> 4) & 1) * 8) * 80 +          \
            ((lane >> 3) & 1) * 16;

#define CHUNK(so)                                                              \
    _Pragma("unroll") for (int kk = 0; kk < 2; ++kk) {                         \
        uint32_t Aa[2][4], Ab[2][4];                                           \
        _Pragma("unroll") for (int mt = 0; mt < 2; ++mt) {                     \
            LDX4(Aa[mt], aav[mt] + (so) + kk * 32);                            \
            LDX4(Ab[mt], aav[mt] + (so) + 10240 + kk * 32);                    \
        }                                                                      \
        _Pragma("unroll") for (int g = 0; g < 2; ++g) {                        \
            uint32_t Ba[4], Bb[4];                                             \
            LDX4(Ba, bbv[g] + (so) + kk * 32);                                 \
            LDX4(Bb, bbv[g] + (so) + 10240 + kk * 32);                         \
            IMMA(acc0[0][2 * g],     Aa[0], Ba[0], Ba[1]);                     \
            IMMA(acc0[1][2 * g],     Aa[1], Ba[0], Ba[1]);                     \
            IMMA(acc0[0][2 * g + 1], Aa[0], Ba[2], Ba[3]);                     \
            IMMA(acc0[1][2 * g + 1], Aa[1], Ba[2], Ba[3]);                     \
            IMMA(acc1[0][2 * g],     Aa[0], Bb[0], Bb[1]);                     \
            IMMA(acc1[1][2 * g],     Aa[1], Bb[0], Bb[1]);                     \
            IMMA(acc1[0][2 * g + 1], Aa[0], Bb[2], Bb[3]);                     \
            IMMA(acc1[1][2 * g + 1], Aa[1], Bb[2], Bb[3]);                     \
            IMMA(acc1[0][2 * g],     Ab[0], Ba[0], Ba[1]);                     \
            IMMA(acc1[1][2 * g],     Ab[1], Ba[0], Ba[1]);                     \
            IMMA(acc1[0][2 * g + 1], Ab[0], Ba[2], Ba[3]);                     \
            IMMA(acc1[1][2 * g + 1], Ab[1], Ba[2], Ba[3]);                     \
        }                                                                      \
    }

#define ACC_INIT()                                                             \
    int acc0[2][4][4], acc1[2][4][4];                                          \
    _Pragma("unroll") for (int i = 0; i < 2; i++)                              \
        _Pragma("unroll") for (int j = 0; j < 4; j++)                          \
            _Pragma("unroll") for (int k = 0; k < 4; k++) {                    \
                acc0[i][j][k] = 0; acc1[i][j][k] = 0; }

// ---------------- fc1: hf = gelu(X[gather] @ W1e^T + b1) (fp32 out) ---------
__global__ __launch_bounds__(512, 1) void k_fc1_i(const float* __restrict__ b1) {
    const int e = blockIdx.z;
    const int cnt = g_cnt[e];
    const int m0 = blockIdx.y * 128;
    if (m0 >= cnt) return;
    const int n0 = blockIdx.x * 128;

    extern __shared__ __align__(128) char smp[];
    const uint32_t sb = smem_u32(smp);
    int*   toks_s = (int*)smp;
    float* bias_s = (float*)(smp + 512);
    float* sm_s   = (float*)(smp + 1024);
    float* sn_s   = (float*)(smp + 1536);
    const int tid = threadIdx.x;
    if (tid < 128) {
        const int tok = g_tok[e * T_TOK + min(m0 + tid, cnt - 1)];
        toks_s[tid] = tok;
        sm_s[tid]   = g_sx[tok];
        bias_s[tid] = b1[e * F_DIM + n0 + tid];
        sn_s[tid]   = g_sw1[e * F_DIM + n0 + tid];
    }
    __syncthreads();

    // staging: q = tid&3 (16B quad), r = tid>>2 (row 0..127); 4 CP16/thread/stage
    const int q = tid & 3, r = tid >> 2;
    const uint32_t dst = sb + SM_HDR + r * 80 + q * 16;
    const size_t aoff = (size_t)toks_s[r] * D_DIM + q * 16;
    const size_t boff = ((size_t)e * F_DIM + n0 + r) * D_DIM + q * 16;

#define STAGE1(c, so) { const uint32_t ko = (uint32_t)(c) * 64;                \
    CP16(dst + (so),         g_xa  + aoff + ko);                               \
    CP16(dst + (so) + 10240, g_xb  + aoff + ko);                               \
    CP16(dst + (so) + 20480, g_w1a + boff + ko);                               \
    CP16(dst + (so) + 30720, g_w1b + boff + ko);                               \
    CP_COMMIT(); }

    LDM_SETUP();
    ACC_INIT();

    const int NC = D_DIM / 64;  // 16
    STAGE1(0, 0); STAGE1(1, STG_SZ); STAGE1(2, 2 * STG_SZ);
    for (int c = 0; c < NC; ++c) {
        CP_WAIT(2);
        __syncthreads();
        if (c + 3 < NC) {
            const int cn = c + 3;
            STAGE1(cn, (uint32_t)(cn & 3) * STG_SZ);
        }
        CHUNK((uint32_t)(c & 3) * STG_SZ);
    }

    // epilogue: dequant + bias + exact gelu -> g_hf (fp32)
    const int gid2 = lane >> 2, tg = lane & 3;
    const int hbase = g_off[e] + m0;
#pragma unroll
    for (int mt = 0; mt < 2; ++mt)
#pragma unroll
        for (int ng = 0; ng < 4; ++ng) {
            const int n = wn + ng * 8 + tg * 2;
            const float bv0 = bias_s[n], bv1 = bias_s[n + 1];
            const float sn0 = sn_s[n],   sn1 = sn_s[n + 1];
#pragma unroll
            for (int h = 0; h < 2; ++h) {
                const int m = wm + mt * 16 + gid2 + h * 8;
                if (m0 + m < cnt) {
                    const float sm = sm_s[m];
                    float v0 = ((float)acc0[mt][ng][2 * h + 0] +
                                (float)acc1[mt][ng][2 * h + 0] * 0.00390625f) * (sm * sn0) + bv0;
                    float v1 = ((float)acc0[mt][ng][2 * h + 1] +
                                (float)acc1[mt][ng][2 * h + 1] * 0.00390625f) * (sm * sn1) + bv1;
                    v0 = 0.5f * v0 * (1.f + erff(v0 * 0.7071067811865476f));
                    v1 = 0.5f * v1 * (1.f + erff(v1 * 0.7071067811865476f));
                    float* hp = g_hf + (size_t)(hbase + m) * F_DIM + (n0 + n);
                    hp[0] = v0; hp[1] = v1;
                }
            }
        }
}

// ---------------- fc2: out[tok] += w * (H @ W2e^T + b2) ---------------------
__global__ __launch_bounds__(512, 1) void k_fc2_i(const float* __restrict__ b2,
                                                  float* __restrict__ out) {
    const int e = blockIdx.z;
    const int cnt = g_cnt[e];
    const int m0 = blockIdx.y * 128;
    if (m0 >= cnt) return;
    const int n0 = blockIdx.x * 128;

    extern __shared__ __align__(128) char smp[];
    const uint32_t sb = smem_u32(smp);
    int*   toks_s = (int*)smp;
    float* bias_s = (float*)(smp + 512);
    float* sm_s   = (float*)(smp + 1024);
    float* sn_s   = (float*)(smp + 1536);
    float* wts_s  = (float*)(smp + 2048);
    const int tid = threadIdx.x;
    if (tid < 128) {
        const int sl = min(m0 + tid, cnt - 1);
        toks_s[tid] = g_tok[e * T_TOK + sl];
        wts_s[tid]  = g_wt [e * T_TOK + sl];
        sm_s[tid]   = g_sh[g_off[e] + sl];
        bias_s[tid] = b2[e * D_DIM + n0 + tid];
        sn_s[tid]   = g_sw2[e * D_DIM + n0 + tid];
    }
    __syncthreads();

    const int q = tid & 3, r = tid >> 2;
    const uint32_t dst = sb + SM_HDR + r * 80 + q * 16;
    const size_t aoff = (size_t)(g_off[e] + min(m0 + r, cnt - 1)) * F_DIM + q * 16;
    const size_t boff = ((size_t)e * D_DIM + n0 + r) * F_DIM + q * 16;

#define STAGE2(c, so) { const uint32_t ko = (uint32_t)(c) * 64;                \
    CP16(dst + (so),         g_ha  + aoff + ko);                               \
    CP16(dst + (so) + 10240, g_hb  + aoff + ko);                               \
    CP16(dst + (so) + 20480, g_w2a + boff + ko);                               \
    CP16(dst + (so) + 30720, g_w2b + boff + ko);                               \
    CP_COMMIT(); }

    LDM_SETUP();
    ACC_INIT();

    const int NC = F_DIM / 64;  // 64
    STAGE2(0, 0); STAGE2(1, STG_SZ); STAGE2(2, 2 * STG_SZ);
    for (int c = 0; c < NC; ++c) {
        CP_WAIT(2);
        __syncthreads();
        if (c + 3 < NC) {
            const int cn = c + 3;
            STAGE2(cn, (uint32_t)(cn & 3) * STG_SZ);
        }
        CHUNK((uint32_t)(c & 3) * STG_SZ);
    }

    // epilogue: dequant + bias, * wt -> atomicAdd scatter (2 adds/elem onto 0)
    const int gid2 = lane >> 2, tg = lane & 3;
#pragma unroll
    for (int mt = 0; mt < 2; ++mt)
#pragma unroll
        for (int ng = 0; ng < 4; ++ng) {
            const int n = wn + ng * 8 + tg * 2;
            const float bv0 = bias_s[n], bv1 = bias_s[n + 1];
            const float sn0 = sn_s[n],   sn1 = sn_s[n + 1];
#pragma unroll
            for (int h = 0; h < 2; ++h) {
                const int m = wm + mt * 16 + gid2 + h * 8;
                if (m0 + m < cnt) {
                    const float sm = sm_s[m], w = wts_s[m];
                    const float v0 = ((float)acc0[mt][ng][2 * h + 0] +
                                      (float)acc1[mt][ng][2 * h + 0] * 0.00390625f) * (sm * sn0) + bv0;
                    const float v1 = ((float)acc0[mt][ng][2 * h + 1] +
                                      (float)acc1[mt][ng][2 * h + 1] * 0.00390625f) * (sm * sn1) + bv1;
                    float* op = out + (size_t)toks_s[m] * D_DIM + n0 + n;
                    atomicAdd(op,     v0 * w);
                    atomicAdd(op + 1, v1 * w);
                }
            }
        }
}

// ---------------- launch -----------------------------------------------------
extern "C" void kernel_launch(void* const* d_in, const int* in_sizes, int n_in,
                              void* d_out, int out_size) {
    const float* x  = (const float*)d_in[0];
    const float* gw = (const float*)d_in[1];
    const float* w1 = (const float*)d_in[2];
    const float* b1 = (const float*)d_in[3];
    const float* w2 = (const float*)d_in[4];
    const float* b2 = (const float*)d_in[5];
    float* out   = (float*)d_out;
    float* probs = out + (size_t)T_TOK * D_DIM;

    // device-global pointers for k_qrows / fc kernels (host cannot take
    // __device__ addresses directly; use cudaGetSymbolAddress-free trick via
    // kernels referencing the symbols — k_qrows takes explicit dst pointers,
    // so resolve them with cudaGetSymbolAddress (not an allocation)).
    static void *pxa = nullptr, *pxb = nullptr, *psx = nullptr;
    static void *pw1a = nullptr, *pw1b = nullptr, *psw1 = nullptr;
    static void *pw2a = nullptr, *pw2b = nullptr, *psw2 = nullptr;
    static void *phf = nullptr, *pha = nullptr, *phb = nullptr, *psh = nullptr;
    if (!pxa) {
        cudaGetSymbolAddress(&pxa, g_xa);   cudaGetSymbolAddress(&pxb, g_xb);
        cudaGetSymbolAddress(&psx, g_sx);
        cudaGetSymbolAddress(&pw1a, g_w1a); cudaGetSymbolAddress(&pw1b, g_w1b);
        cudaGetSymbolAddress(&psw1, g_sw1);
        cudaGetSymbolAddress(&pw2a, g_w2a); cudaGetSymbolAddress(&pw2b, g_w2b);
        cudaGetSymbolAddress(&psw2, g_sw2);
        cudaGetSymbolAddress(&phf, g_hf);   cudaGetSymbolAddress(&pha, g_ha);
        cudaGetSymbolAddress(&phb, g_hb);   cudaGetSymbolAddress(&psh, g_sh);
    }

    cudaFuncSetAttribute(k_fc1_i, cudaFuncAttributeMaxDynamicSharedMemorySize, SMEM_DYN);
    cudaFuncSetAttribute(k_fc2_i, cudaFuncAttributeMaxDynamicSharedMemorySize, SMEM_DYN);

    k_init<<<512, 256>>>((float4*)out);
    k_qrows<<<T_TOK, 256>>>(x,  (int8_t*)pxa,  (int8_t*)pxb,  (float*)psx,  D_DIM);
    k_qrows<<<E_EXP * F_DIM, 256>>>(w1, (int8_t*)pw1a, (int8_t*)pw1b, (float*)psw1, D_DIM);
    k_qrows<<<E_EXP * D_DIM, 256>>>(w2, (int8_t*)pw2a, (int8_t*)pw2b, (float*)psw2, F_DIM);
    k_gate<<<T_TOK / 8, 256>>>(x, gw, probs);
    k_prefix<<<1, 32>>>();
    k_fc1_i<<<dim3(F_DIM / 128, T_TOK / 128, E_EXP), 512, SMEM_DYN>>>(b1);
    k_qrows<<<NSLOT, 256>>>((const float*)phf, (int8_t*)pha, (int8_t*)phb, (float*)psh, F_DIM);
    k_fc2_i<<<dim3(D_DIM / 128, T_TOK / 128, E_EXP), 512, SMEM_DYN>>>(b2, out);
}

// round 7
// speedup vs baseline: 6.4316x; 6.4316x over previous
#include <cuda_runtime.h>
#include <cuda_fp16.h>
#include <math.h>
#include <stdint.h>

#define T_TOK 8192
#define D_DIM 1024
#define F_DIM 4096
#define E_EXP 8

// ---------------- scratch (static device globals; no allocations) ----------
__device__ int    g_cnt[E_EXP];
__device__ int    g_off[E_EXP];
__device__ int    g_tok[E_EXP * T_TOK];
__device__ float  g_wt [E_EXP * T_TOK];

__device__ __half g_xh [(size_t)T_TOK * D_DIM];
__device__ __half g_w1h[(size_t)E_EXP * F_DIM * D_DIM];
__device__ __half g_w2h[(size_t)E_EXP * D_DIM * F_DIM];
__device__ __half g_hh [(size_t)2 * T_TOK * F_DIM];

// ---------------- PTX helpers (sm_80+ features only) ------------------------
__device__ __forceinline__ uint32_t smem_u32(const void* p) {
    uint32_t a;
    asm("{ .reg .u64 t; cvta.to.shared.u64 t, %1; cvt.u32.u64 %0, t; }" : "=r"(a) : "l"(p));
    return a;
}
#define CP16(dst, src) asm volatile("cp.async.cg.shared.global [%0], [%1], 16;" :: "r"(dst), "l"(src) : "memory")
#define CP_COMMIT()    asm volatile("cp.async.commit_group;" ::: "memory")
#define CP_WAIT(n)     asm volatile("cp.async.wait_group %0;" :: "n"(n) : "memory")
#define LDX4(r, a)                                                             \
    asm volatile("ldmatrix.sync.aligned.m8n8.x4.shared.b16 {%0,%1,%2,%3}, [%4];" \
        : "=r"((r)[0]), "=r"((r)[1]), "=r"((r)[2]), "=r"((r)[3]) : "r"(a))
#define MMAH(d, a, b0, b1)                                                     \
    asm volatile("mma.sync.aligned.m16n8k16.row.col.f32.f16.f16.f32 "          \
        "{%0,%1,%2,%3},{%4,%5,%6,%7},{%8,%9},{%0,%1,%2,%3};"                   \
        : "+f"((d)[0]), "+f"((d)[1]), "+f"((d)[2]), "+f"((d)[3])               \
        : "r"((a)[0]), "r"((a)[1]), "r"((a)[2]), "r"((a)[3]), "r"(b0), "r"(b1))

__device__ __forceinline__ uint32_t pack_h(__half a, __half b) {
    return ((uint32_t)__half_as_ushort(b) << 16) | __half_as_ushort(a);
}

// SMEM: toks @0 (512B), bias @512 (512B), wts @1024 (512B), stages @2048.
// Stage (k-chunk 64 fp16 = 128B, pitch 144B): A @0 (128x144), B @18432.
#define SM_HDR  2048
#define PITCH   144
#define STG_SZ  36864
#define SMEM_DYN (SM_HDR + 2 * STG_SZ)

// ---------------- init ------------------------------------------------------
__global__ void k_init(float4* __restrict__ out4) {
    int i = blockIdx.x * blockDim.x + threadIdx.x;
    if (i < E_EXP) g_cnt[i] = 0;
    const size_t n4 = (size_t)T_TOK * D_DIM / 4;
    float4 z = make_float4(0.f, 0.f, 0.f, 0.f);
    for (size_t j = i; j < n4; j += (size_t)gridDim.x * blockDim.x) out4[j] = z;
}

// ---------------- convert fp32 -> fp16 ---------------------------------------
__global__ void k_split(const float* __restrict__ x, const float* __restrict__ w1,
                        const float* __restrict__ w2) {
    size_t stride = (size_t)gridDim.x * blockDim.x;
    size_t i0 = (size_t)blockIdx.x * blockDim.x + threadIdx.x;
    const size_t nx4 = (size_t)T_TOK * D_DIM / 4;
    const size_t nw4 = (size_t)E_EXP * F_DIM * D_DIM / 4;
    uint2* xo  = (uint2*)g_xh;
    uint2* w1o = (uint2*)g_w1h;
    uint2* w2o = (uint2*)g_w2h;
    for (size_t i = i0; i < nx4; i += stride) {
        float4 f = ((const float4*)x)[i];
        xo[i] = make_uint2(pack_h(__float2half_rn(f.x), __float2half_rn(f.y)),
                           pack_h(__float2half_rn(f.z), __float2half_rn(f.w)));
    }
    for (size_t i = i0; i < nw4; i += stride) {
        float4 f = ((const float4*)w1)[i];
        w1o[i] = make_uint2(pack_h(__float2half_rn(f.x), __float2half_rn(f.y)),
                            pack_h(__float2half_rn(f.z), __float2half_rn(f.w)));
    }
    for (size_t i = i0; i < nw4; i += stride) {
        float4 f = ((const float4*)w2)[i];
        w2o[i] = make_uint2(pack_h(__float2half_rn(f.x), __float2half_rn(f.y)),
                            pack_h(__float2half_rn(f.z), __float2half_rn(f.w)));
    }
}

// ---------------- gating (validated) ----------------------------------------
__global__ void k_gate(const float* __restrict__ x, const float* __restrict__ gw,
                       float* __restrict__ probs_out) {
    int warp = (blockIdx.x * blockDim.x + threadIdx.x) >> 5;
    int lane = threadIdx.x & 31;
    if (warp >= T_TOK) return;
    const float* xr = x + (size_t)warp * D_DIM;
    float acc[E_EXP];
#pragma unroll
    for (int e = 0; e < E_EXP; e++) acc[e] = 0.f;
    for (int k = lane * 4; k < D_DIM; k += 128) {
        float4 xv = *(const float4*)(xr + k);
#pragma unroll
        for (int e = 0; e < E_EXP; e++) {
            float4 wv = *(const float4*)(gw + (size_t)e * D_DIM + k);
            acc[e] += xv.x * wv.x + xv.y * wv.y + xv.z * wv.z + xv.w * wv.w;
        }
    }
#pragma unroll
    for (int e = 0; e < E_EXP; e++)
#pragma unroll
        for (int o = 16; o > 0; o >>= 1) acc[e] += __shfl_xor_sync(0xffffffffu, acc[e], o);
    if (lane == 0) {
        float mx = acc[0];
#pragma unroll
        for (int e = 1; e < E_EXP; e++) mx = fmaxf(mx, acc[e]);
        float p[E_EXP], s = 0.f;
#pragma unroll
        for (int e = 0; e < E_EXP; e++) { p[e] = expf(acc[e] - mx); s += p[e]; }
        float inv = 1.f / s;
#pragma unroll
        for (int e = 0; e < E_EXP; e++) {
            p[e] *= inv;
            probs_out[(size_t)warp * E_EXP + e] = p[e];
        }
        int i0 = 0;
#pragma unroll
        for (int e = 1; e < E_EXP; e++) if (p[e] > p[i0]) i0 = e;
        int i1 = (i0 == 0) ? 1 : 0;
#pragma unroll
        for (int e = 0; e < E_EXP; e++) if (e != i0 && p[e] > p[i1]) i1 = e;
        float denom = p[i0] + p[i1] + 1e-9f;
        int s0 = atomicAdd(&g_cnt[i0], 1);
        g_tok[i0 * T_TOK + s0] = warp; g_wt[i0 * T_TOK + s0] = p[i0] / denom;
        int s1 = atomicAdd(&g_cnt[i1], 1);
        g_tok[i1 * T_TOK + s1] = warp; g_wt[i1 * T_TOK + s1] = p[i1] / denom;
    }
}
__global__ void k_prefix() {
    if (threadIdx.x == 0) {
        int run = 0;
#pragma unroll
        for (int e = 0; e < E_EXP; e++) { g_off[e] = run; run += g_cnt[e]; }
    }
}

// ---------------- GEMM core: block 128x128xk64, 8 warps, warp 32x64 ---------
#define LDM_SETUP()                                                            \
    const int lane = tid & 31, wid = tid >> 5;                                 \
    const int wm = (wid & 3) * 32, wn = (wid >> 2) * 64;                       \
    uint32_t aav[2];                                                           \
    _Pragma("unroll") for (int mt = 0; mt < 2; ++mt)                           \
        aav[mt] = sb + SM_HDR + (wm + mt * 16 + (lane & 15)) * PITCH +         \
                  ((lane >> 4) & 1) * 16;                                      \
    uint32_t bbv[4];                                                           \
    _Pragma("unroll") for (int g = 0; g < 4; ++g)                              \
        bbv[g] = sb + SM_HDR + 18432 +                                         \
            (wn + g * 16 + (lane & 7) + ((lane >> 4) & 1) * 8) * PITCH +       \
            ((lane >> 3) & 1) * 16;

#define CHUNK(so)                                                              \
    _Pragma("unroll") for (int kk = 0; kk < 4; ++kk) {                         \
        uint32_t Ah[2][4];                                                     \
        LDX4(Ah[0], aav[0] + (so) + kk * 32);                                  \
        LDX4(Ah[1], aav[1] + (so) + kk * 32);                                  \
        _Pragma("unroll") for (int g = 0; g < 4; ++g) {                        \
            uint32_t Bh[4];                                                    \
            LDX4(Bh, bbv[g] + (so) + kk * 32);                                 \
            MMAH(acc[0][2 * g],     Ah[0], Bh[0], Bh[1]);                      \
            MMAH(acc[1][2 * g],     Ah[1], Bh[0], Bh[1]);                      \
            MMAH(acc[0][2 * g + 1], Ah[0], Bh[2], Bh[3]);                      \
            MMAH(acc[1][2 * g + 1], Ah[1], Bh[2], Bh[3]);                      \
        }                                                                      \
    }

#define ACC_INIT()                                                             \
    float acc[2][8][4];                                                        \
    _Pragma("unroll") for (int i = 0; i < 2; i++)                              \
        _Pragma("unroll") for (int j = 0; j < 8; j++)                          \
            _Pragma("unroll") for (int k = 0; k < 4; k++) acc[i][j][k] = 0.f;

// ---------------- fc1: h = gelu(X[gather] @ W1e^T + b1) -> fp16 -------------
__global__ __launch_bounds__(256, 2) void k_fc1_h(const float* __restrict__ b1) {
    const int e = blockIdx.z;
    const int cnt = g_cnt[e];
    const int m0 = blockIdx.y * 128;
    if (m0 >= cnt) return;
    const int n0 = blockIdx.x * 128;

    extern __shared__ __align__(128) char smp[];
    const uint32_t sb = smem_u32(smp);
    int*   toks_s = (int*)smp;
    float* bias_s = (float*)(smp + 512);
    const int tid = threadIdx.x;
    if (tid < 128) {
        toks_s[tid] = g_tok[e * T_TOK + min(m0 + tid, cnt - 1)];
        bias_s[tid] = b1[e * F_DIM + n0 + tid];
    }
    __syncthreads();

    // staging: q = tid&7 (16B quad of 128B row), r = tid>>3 (0..31), rows r+32j
    const int q = tid & 7, r = tid >> 3;
    const uint32_t dA = sb + SM_HDR + r * PITCH + q * 16;
    const uint32_t dB = dA + 18432;
    const char* xp = (const char*)g_xh;
    size_t aoff[4];
    const char* wp[4];
#pragma unroll
    for (int j = 0; j < 4; ++j) {
        aoff[j] = (size_t)toks_s[r + 32 * j] * (D_DIM * 2) + q * 16;
        wp[j] = (const char*)(g_w1h + ((size_t)e * F_DIM + n0 + r + 32 * j) * D_DIM) + q * 16;
    }

#define STAGE1(c, so) { const uint32_t ko = (uint32_t)(c) * 128;               \
    _Pragma("unroll") for (int j = 0; j < 4; ++j) {                            \
        CP16(dA + (so) + j * (32 * PITCH), xp + aoff[j] + ko);                 \
        CP16(dB + (so) + j * (32 * PITCH), wp[j] + ko);                        \
    }                                                                          \
    CP_COMMIT(); }

    LDM_SETUP();
    ACC_INIT();

    STAGE1(0, 0);
    const int NC = D_DIM / 64;  // 16
    for (int c = 0; c < NC; ++c) {
        const uint32_t so = (uint32_t)(c & 1) * STG_SZ;
        if (c + 1 < NC) { STAGE1(c + 1, (uint32_t)((c + 1) & 1) * STG_SZ); CP_WAIT(1); }
        else            { CP_WAIT(0); }
        __syncthreads();
        CHUNK(so);
        __syncthreads();
    }

    // epilogue: bias + exact gelu -> fp16 -> g_hh
    const int gid2 = lane >> 2, tg = lane & 3;
    const int hbase = g_off[e] + m0;
    uint32_t* gh = (uint32_t*)g_hh;
#pragma unroll
    for (int mt = 0; mt < 2; ++mt)
#pragma unroll
        for (int nt = 0; nt < 8; ++nt) {
            const int n = wn + nt * 8 + tg * 2;
            const float bv0 = bias_s[n], bv1 = bias_s[n + 1];
#pragma unroll
            for (int h = 0; h < 2; ++h) {
                const int m = wm + mt * 16 + gid2 + h * 8;
                if (m0 + m < cnt) {
                    float v0 = acc[mt][nt][2 * h + 0] + bv0;
                    float v1 = acc[mt][nt][2 * h + 1] + bv1;
                    v0 = 0.5f * v0 * (1.f + erff(v0 * 0.7071067811865476f));
                    v1 = 0.5f * v1 * (1.f + erff(v1 * 0.7071067811865476f));
                    gh[(size_t)(hbase + m) * (F_DIM / 2) + (size_t)(n0 + n) / 2] =
                        pack_h(__float2half_rn(v0), __float2half_rn(v1));
                }
            }
        }
}

// ---------------- fc2: out[tok] += w * (H @ W2e^T + b2) ---------------------
__global__ __launch_bounds__(256, 2) void k_fc2_h(const float* __restrict__ b2,
                                                  float* __restrict__ out) {
    const int e = blockIdx.z;
    const int cnt = g_cnt[e];
    const int m0 = blockIdx.y * 128;
    if (m0 >= cnt) return;
    const int n0 = blockIdx.x * 128;

    extern __shared__ __align__(128) char smp[];
    const uint32_t sb = smem_u32(smp);
    int*   toks_s = (int*)smp;
    float* bias_s = (float*)(smp + 512);
    float* wts_s  = (float*)(smp + 1024);
    const int tid = threadIdx.x;
    if (tid < 128) {
        const int sl = min(m0 + tid, cnt - 1);
        toks_s[tid] = g_tok[e * T_TOK + sl];
        wts_s[tid]  = g_wt [e * T_TOK + sl];
        bias_s[tid] = b2[e * D_DIM + n0 + tid];
    }
    __syncthreads();

    const int q = tid & 7, r = tid >> 3;
    const uint32_t dA = sb + SM_HDR + r * PITCH + q * 16;
    const uint32_t dB = dA + 18432;
    const char* hp = (const char*)g_hh;
    size_t aoff[4];
    const char* wp[4];
#pragma unroll
    for (int j = 0; j < 4; ++j) {
        aoff[j] = (size_t)(g_off[e] + min(m0 + r + 32 * j, cnt - 1)) * (F_DIM * 2) + q * 16;
        wp[j] = (const char*)(g_w2h + ((size_t)e * D_DIM + n0 + r + 32 * j) * F_DIM) + q * 16;
    }

#define STAGE2(c, so) { const uint32_t ko = (uint32_t)(c) * 128;               \
    _Pragma("unroll") for (int j = 0; j < 4; ++j) {                            \
        CP16(dA + (so) + j * (32 * PITCH), hp + aoff[j] + ko);                 \
        CP16(dB + (so) + j * (32 * PITCH), wp[j] + ko);                        \
    }                                                                          \
    CP_COMMIT(); }

    LDM_SETUP();
    ACC_INIT();

    STAGE2(0, 0);
    const int NC = F_DIM / 64;  // 64
    for (int c = 0; c < NC; ++c) {
        const uint32_t so = (uint32_t)(c & 1) * STG_SZ;
        if (c + 1 < NC) { STAGE2(c + 1, (uint32_t)((c + 1) & 1) * STG_SZ); CP_WAIT(1); }
        else            { CP_WAIT(0); }
        __syncthreads();
        CHUNK(so);
        __syncthreads();
    }

    // epilogue: (acc + bias) * wt -> atomicAdd scatter (2 adds/elem onto 0)
    const int gid2 = lane >> 2, tg = lane & 3;
#pragma unroll
    for (int mt = 0; mt < 2; ++mt)
#pragma unroll
        for (int nt = 0; nt < 8; ++nt) {
            const int n = wn + nt * 8 + tg * 2;
            const float bv0 = bias_s[n], bv1 = bias_s[n + 1];
#pragma unroll
            for (int h = 0; h < 2; ++h) {
                const int m = wm + mt * 16 + gid2 + h * 8;
                if (m0 + m < cnt) {
                    const int   t = toks_s[m];
                    const float w = wts_s[m];
                    float* op = out + (size_t)t * D_DIM + n0 + n;
                    atomicAdd(op,     (acc[mt][nt][2 * h + 0] + bv0) * w);
                    atomicAdd(op + 1, (acc[mt][nt][2 * h + 1] + bv1) * w);
                }
            }
        }
}

// ---------------- launch -----------------------------------------------------
extern "C" void kernel_launch(void* const* d_in, const int* in_sizes, int n_in,
                              void* d_out, int out_size) {
    const float* x  = (const float*)d_in[0];
    const float* gw = (const float*)d_in[1];
    const float* w1 = (const float*)d_in[2];
    const float* b1 = (const float*)d_in[3];
    const float* w2 = (const float*)d_in[4];
    const float* b2 = (const float*)d_in[5];
    float* out   = (float*)d_out;
    float* probs = out + (size_t)T_TOK * D_DIM;

    cudaFuncSetAttribute(k_fc1_h, cudaFuncAttributeMaxDynamicSharedMemorySize, SMEM_DYN);
    cudaFuncSetAttribute(k_fc2_h, cudaFuncAttributeMaxDynamicSharedMemorySize, SMEM_DYN);

    k_init<<<512, 256>>>((float4*)out);
    k_split<<<1024, 256>>>(x, w1, w2);
    k_gate<<<T_TOK / 8, 256>>>(x, gw, probs);
    k_prefix<<<1, 32>>>();
    k_fc1_h<<<dim3(F_DIM / 128, T_TOK / 128, E_EXP), 256, SMEM_DYN>>>(b1);
    k_fc2_h<<<dim3(D_DIM / 128, T_TOK / 128, E_EXP), 256, SMEM_DYN>>>(b2, out);
}

// round 8
// speedup vs baseline: 6.5242x; 1.0144x over previous
#include <cuda_runtime.h>
#include <cuda_fp16.h>
#include <math.h>
#include <stdint.h>

#define T_TOK 8192
#define D_DIM 1024
#define F_DIM 4096
#define E_EXP 8

// ---------------- scratch (static device globals; no allocations) ----------
__device__ int    g_cnt[E_EXP];
__device__ int    g_off[E_EXP];
__device__ int    g_tok[E_EXP * T_TOK];
__device__ float  g_wt [E_EXP * T_TOK];

__device__ __half g_xh [(size_t)T_TOK * D_DIM];
__device__ __half g_w1h[(size_t)E_EXP * F_DIM * D_DIM];
__device__ __half g_w2h[(size_t)E_EXP * D_DIM * F_DIM];
__device__ __half g_hh [(size_t)2 * T_TOK * F_DIM];

// ---------------- PTX helpers (sm_80+ features only) ------------------------
__device__ __forceinline__ uint32_t smem_u32(const void* p) {
    uint32_t a;
    asm("{ .reg .u64 t; cvta.to.shared.u64 t, %1; cvt.u32.u64 %0, t; }" : "=r"(a) : "l"(p));
    return a;
}
#define CP16(dst, src) asm volatile("cp.async.cg.shared.global [%0], [%1], 16;" :: "r"(dst), "l"(src) : "memory")
#define CP_COMMIT()    asm volatile("cp.async.commit_group;" ::: "memory")
#define CP_WAIT(n)     asm volatile("cp.async.wait_group %0;" :: "n"(n) : "memory")
#define LDX4(r, a)                                                             \
    asm volatile("ldmatrix.sync.aligned.m8n8.x4.shared.b16 {%0,%1,%2,%3}, [%4];" \
        : "=r"((r)[0]), "=r"((r)[1]), "=r"((r)[2]), "=r"((r)[3]) : "r"(a))
#define MMAH(d, a, b0, b1)                                                     \
    asm volatile("mma.sync.aligned.m16n8k16.row.col.f32.f16.f16.f32 "          \
        "{%0,%1,%2,%3},{%4,%5,%6,%7},{%8,%9},{%0,%1,%2,%3};"                   \
        : "+f"((d)[0]), "+f"((d)[1]), "+f"((d)[2]), "+f"((d)[3])               \
        : "r"((a)[0]), "r"((a)[1]), "r"((a)[2]), "r"((a)[3]), "r"(b0), "r"(b1))

__device__ __forceinline__ uint32_t pack_h(__half a, __half b) {
    return ((uint32_t)__half_as_ushort(b) << 16) | __half_as_ushort(a);
}

// SMEM: toks @0 (512B), bias @512 (512B), wts @1024 (512B), stages @2048.
// Stage (k-chunk 64 fp16 = 128B, pitch 144B): A @0 (128x144), B @18432.
#define SM_HDR  2048
#define PITCH   144
#define STG_SZ  36864
#define SMEM_DYN (SM_HDR + 2 * STG_SZ)

// ---------------- init ------------------------------------------------------
__global__ void k_init(float4* __restrict__ out4) {
    int i = blockIdx.x * blockDim.x + threadIdx.x;
    if (i < E_EXP) g_cnt[i] = 0;
    const size_t n4 = (size_t)T_TOK * D_DIM / 4;
    float4 z = make_float4(0.f, 0.f, 0.f, 0.f);
    for (size_t j = i; j < n4; j += (size_t)gridDim.x * blockDim.x) out4[j] = z;
}

// ---------------- convert fp32 -> fp16 ---------------------------------------
__global__ void k_split(const float* __restrict__ x, const float* __restrict__ w1,
                        const float* __restrict__ w2) {
    size_t stride = (size_t)gridDim.x * blockDim.x;
    size_t i0 = (size_t)blockIdx.x * blockDim.x + threadIdx.x;
    const size_t nx4 = (size_t)T_TOK * D_DIM / 4;
    const size_t nw4 = (size_t)E_EXP * F_DIM * D_DIM / 4;
    uint2* xo  = (uint2*)g_xh;
    uint2* w1o = (uint2*)g_w1h;
    uint2* w2o = (uint2*)g_w2h;
    for (size_t i = i0; i < nx4; i += stride) {
        float4 f = ((const float4*)x)[i];
        xo[i] = make_uint2(pack_h(__float2half_rn(f.x), __float2half_rn(f.y)),
                           pack_h(__float2half_rn(f.z), __float2half_rn(f.w)));
    }
    for (size_t i = i0; i < nw4; i += stride) {
        float4 f = ((const float4*)w1)[i];
        w1o[i] = make_uint2(pack_h(__float2half_rn(f.x), __float2half_rn(f.y)),
                            pack_h(__float2half_rn(f.z), __float2half_rn(f.w)));
    }
    for (size_t i = i0; i < nw4; i += stride) {
        float4 f = ((const float4*)w2)[i];
        w2o[i] = make_uint2(pack_h(__float2half_rn(f.x), __float2half_rn(f.y)),
                            pack_h(__float2half_rn(f.z), __float2half_rn(f.w)));
    }
}

// ---------------- gating (validated) ----------------------------------------
__global__ void k_gate(const float* __restrict__ x, const float* __restrict__ gw,
                       float* __restrict__ probs_out) {
    int warp = (blockIdx.x * blockDim.x + threadIdx.x) >> 5;
    int lane = threadIdx.x & 31;
    if (warp >= T_TOK) return;
    const float* xr = x + (size_t)warp * D_DIM;
    float acc[E_EXP];
#pragma unroll
    for (int e = 0; e < E_EXP; e++) acc[e] = 0.f;
    for (int k = lane * 4; k < D_DIM; k += 128) {
        float4 xv = *(const float4*)(xr + k);
#pragma unroll
        for (int e = 0; e < E_EXP; e++) {
            float4 wv = *(const float4*)(gw + (size_t)e * D_DIM + k);
            acc[e] += xv.x * wv.x + xv.y * wv.y + xv.z * wv.z + xv.w * wv.w;
        }
    }
#pragma unroll
    for (int e = 0; e < E_EXP; e++)
#pragma unroll
        for (int o = 16; o > 0; o >>= 1) acc[e] += __shfl_xor_sync(0xffffffffu, acc[e], o);
    if (lane == 0) {
        float mx = acc[0];
#pragma unroll
        for (int e = 1; e < E_EXP; e++) mx = fmaxf(mx, acc[e]);
        float p[E_EXP], s = 0.f;
#pragma unroll
        for (int e = 0; e < E_EXP; e++) { p[e] = expf(acc[e] - mx); s += p[e]; }
        float inv = 1.f / s;
#pragma unroll
        for (int e = 0; e < E_EXP; e++) {
            p[e] *= inv;
            probs_out[(size_t)warp * E_EXP + e] = p[e];
        }
        int i0 = 0;
#pragma unroll
        for (int e = 1; e < E_EXP; e++) if (p[e] > p[i0]) i0 = e;
        int i1 = (i0 == 0) ? 1 : 0;
#pragma unroll
        for (int e = 0; e < E_EXP; e++) if (e != i0 && p[e] > p[i1]) i1 = e;
        float denom = p[i0] + p[i1] + 1e-9f;
        int s0 = atomicAdd(&g_cnt[i0], 1);
        g_tok[i0 * T_TOK + s0] = warp; g_wt[i0 * T_TOK + s0] = p[i0] / denom;
        int s1 = atomicAdd(&g_cnt[i1], 1);
        g_tok[i1 * T_TOK + s1] = warp; g_wt[i1 * T_TOK + s1] = p[i1] / denom;
    }
}
__global__ void k_prefix() {
    if (threadIdx.x == 0) {
        int run = 0;
#pragma unroll
        for (int e = 0; e < E_EXP; e++) { g_off[e] = run; run += g_cnt[e]; }
    }
}

// ---------------- GEMM core: block 128x128xk64, 8 warps, warp 32x64 ---------
#define LDM_SETUP()                                                            \
    const int lane = tid & 31, wid = tid >> 5;                                 \
    const int wm = (wid & 3) * 32, wn = (wid >> 2) * 64;                       \
    uint32_t aav[2];                                                           \
    _Pragma("unroll") for (int mt = 0; mt < 2; ++mt)                           \
        aav[mt] = sb + SM_HDR + (wm + mt * 16 + (lane & 15)) * PITCH +         \
                  ((lane >> 4) & 1) * 16;                                      \
    uint32_t bbv[4];                                                           \
    _Pragma("unroll") for (int g = 0; g < 4; ++g)                              \
        bbv[g] = sb + SM_HDR + 18432 +                                         \
            (wn + g * 16 + (lane & 7) + ((lane >> 4) & 1) * 8) * PITCH +       \
            ((lane >> 3) & 1) * 16;

// Fragment-pipelined chunk: B group g+1 and A chunk kk+1 are ldmatrix'd while
// group g's 4 MMAs issue, hiding LDSM latency. Per-accumulator MMA order is
// identical to the non-pipelined version => bit-identical numerics.
#define CHUNK(so) {                                                            \
    uint32_t Ah[2][2][4], Bh[2][4];                                            \
    LDX4(Ah[0][0], aav[0] + (so));                                             \
    LDX4(Ah[0][1], aav[1] + (so));                                             \
    LDX4(Bh[0], bbv[0] + (so));                                                \
    _Pragma("unroll") for (int kk = 0; kk < 4; ++kk) {                         \
        _Pragma("unroll") for (int g = 0; g < 4; ++g) {                        \
            const int cur = g & 1, nxt = cur ^ 1;                              \
            if (g < 3)       { LDX4(Bh[nxt], bbv[g + 1] + (so) + kk * 32); }   \
            else if (kk < 3) { LDX4(Bh[nxt], bbv[0] + (so) + (kk + 1) * 32); } \
            if (g == 0 && kk < 3) {                                            \
                LDX4(Ah[(kk + 1) & 1][0], aav[0] + (so) + (kk + 1) * 32);      \
                LDX4(Ah[(kk + 1) & 1][1], aav[1] + (so) + (kk + 1) * 32);      \
            }                                                                  \
            MMAH(acc[0][2 * g],     Ah[kk & 1][0], Bh[cur][0], Bh[cur][1]);    \
            MMAH(acc[1][2 * g],     Ah[kk & 1][1], Bh[cur][0], Bh[cur][1]);    \
            MMAH(acc[0][2 * g + 1], Ah[kk & 1][0], Bh[cur][2], Bh[cur][3]);    \
            MMAH(acc[1][2 * g + 1], Ah[kk & 1][1], Bh[cur][2], Bh[cur][3]);    \
        }                                                                      \
    }                                                                          \
}

#define ACC_INIT()                                                             \
    float acc[2][8][4];                                                        \
    _Pragma("unroll") for (int i = 0; i < 2; i++)                              \
        _Pragma("unroll") for (int j = 0; j < 8; j++)                          \
            _Pragma("unroll") for (int k = 0; k < 4; k++) acc[i][j][k] = 0.f;

// ---------------- fc1: h = gelu(X[gather] @ W1e^T + b1) -> fp16 -------------
__global__ __launch_bounds__(256, 2) void k_fc1_h(const float* __restrict__ b1) {
    const int e = blockIdx.z;
    const int cnt = g_cnt[e];
    const int m0 = blockIdx.y * 128;
    if (m0 >= cnt) return;
    const int n0 = blockIdx.x * 128;

    extern __shared__ __align__(128) char smp[];
    const uint32_t sb = smem_u32(smp);
    int*   toks_s = (int*)smp;
    float* bias_s = (float*)(smp + 512);
    const int tid = threadIdx.x;
    if (tid < 128) {
        toks_s[tid] = g_tok[e * T_TOK + min(m0 + tid, cnt - 1)];
        bias_s[tid] = b1[e * F_DIM + n0 + tid];
    }
    __syncthreads();

    // staging: q = tid&7 (16B quad of 128B row), r = tid>>3 (0..31), rows r+32j
    const int q = tid & 7, r = tid >> 3;
    const uint32_t dA = sb + SM_HDR + r * PITCH + q * 16;
    const uint32_t dB = dA + 18432;
    const char* xp = (const char*)g_xh;
    size_t aoff[4];
    const char* wp[4];
#pragma unroll
    for (int j = 0; j < 4; ++j) {
        aoff[j] = (size_t)toks_s[r + 32 * j] * (D_DIM * 2) + q * 16;
        wp[j] = (const char*)(g_w1h + ((size_t)e * F_DIM + n0 + r + 32 * j) * D_DIM) + q * 16;
    }

#define STAGE1(c, so) { const uint32_t ko = (uint32_t)(c) * 128;               \
    _Pragma("unroll") for (int j = 0; j < 4; ++j) {                            \
        CP16(dA + (so) + j * (32 * PITCH), xp + aoff[j] + ko);                 \
        CP16(dB + (so) + j * (32 * PITCH), wp[j] + ko);                        \
    }                                                                          \
    CP_COMMIT(); }

    LDM_SETUP();
    ACC_INIT();

    STAGE1(0, 0);
    const int NC = D_DIM / 64;  // 16
    for (int c = 0; c < NC; ++c) {
        const uint32_t so = (uint32_t)(c & 1) * STG_SZ;
        if (c + 1 < NC) { STAGE1(c + 1, (uint32_t)((c + 1) & 1) * STG_SZ); CP_WAIT(1); }
        else            { CP_WAIT(0); }
        __syncthreads();
        CHUNK(so);
        __syncthreads();
    }

    // epilogue: bias + exact gelu -> fp16 -> g_hh
    const int gid2 = lane >> 2, tg = lane & 3;
    const int hbase = g_off[e] + m0;
    uint32_t* gh = (uint32_t*)g_hh;
#pragma unroll
    for (int mt = 0; mt < 2; ++mt)
#pragma unroll
        for (int nt = 0; nt < 8; ++nt) {
            const int n = wn + nt * 8 + tg * 2;
            const float bv0 = bias_s[n], bv1 = bias_s[n + 1];
#pragma unroll
            for (int h = 0; h < 2; ++h) {
                const int m = wm + mt * 16 + gid2 + h * 8;
                if (m0 + m < cnt) {
                    float v0 = acc[mt][nt][2 * h + 0] + bv0;
                    float v1 = acc[mt][nt][2 * h + 1] + bv1;
                    v0 = 0.5f * v0 * (1.f + erff(v0 * 0.7071067811865476f));
                    v1 = 0.5f * v1 * (1.f + erff(v1 * 0.7071067811865476f));
                    gh[(size_t)(hbase + m) * (F_DIM / 2) + (size_t)(n0 + n) / 2] =
                        pack_h(__float2half_rn(v0), __float2half_rn(v1));
                }
            }
        }
}

// ---------------- fc2: out[tok] += w * (H @ W2e^T + b2) ---------------------
__global__ __launch_bounds__(256, 2) void k_fc2_h(const float* __restrict__ b2,
                                                  float* __restrict__ out) {
    const int e = blockIdx.z;
    const int cnt = g_cnt[e];
    const int m0 = blockIdx.y * 128;
    if (m0 >= cnt) return;
    const int n0 = blockIdx.x * 128;

    extern __shared__ __align__(128) char smp[];
    const uint32_t sb = smem_u32(smp);
    int*   toks_s = (int*)smp;
    float* bias_s = (float*)(smp + 512);
    float* wts_s  = (float*)(smp + 1024);
    const int tid = threadIdx.x;
    if (tid < 128) {
        const int sl = min(m0 + tid, cnt - 1);
        toks_s[tid] = g_tok[e * T_TOK + sl];
        wts_s[tid]  = g_wt [e * T_TOK + sl];
        bias_s[tid] = b2[e * D_DIM + n0 + tid];
    }
    __syncthreads();

    const int q = tid & 7, r = tid >> 3;
    const uint32_t dA = sb + SM_HDR + r * PITCH + q * 16;
    const uint32_t dB = dA + 18432;
    const char* hp = (const char*)g_hh;
    size_t aoff[4];
    const char* wp[4];
#pragma unroll
    for (int j = 0; j < 4; ++j) {
        aoff[j] = (size_t)(g_off[e] + min(m0 + r + 32 * j, cnt - 1)) * (F_DIM * 2) + q * 16;
        wp[j] = (const char*)(g_w2h + ((size_t)e * D_DIM + n0 + r + 32 * j) * F_DIM) + q * 16;
    }

#define STAGE2(c, so) { const uint32_t ko = (uint32_t)(c) * 128;               \
    _Pragma("unroll") for (int j = 0; j < 4; ++j) {                            \
        CP16(dA + (so) + j * (32 * PITCH), hp + aoff[j] + ko);                 \
        CP16(dB + (so) + j * (32 * PITCH), wp[j] + ko);                        \
    }                                                                          \
    CP_COMMIT(); }

    LDM_SETUP();
    ACC_INIT();

    STAGE2(0, 0);
    const int NC = F_DIM / 64;  // 64
    for (int c = 0; c < NC; ++c) {
        const uint32_t so = (uint32_t)(c & 1) * STG_SZ;
        if (c + 1 < NC) { STAGE2(c + 1, (uint32_t)((c + 1) & 1) * STG_SZ); CP_WAIT(1); }
        else            { CP_WAIT(0); }
        __syncthreads();
        CHUNK(so);
        __syncthreads();
    }

    // epilogue: (acc + bias) * wt -> atomicAdd scatter (2 adds/elem onto 0)
    const int gid2 = lane >> 2, tg = lane & 3;
#pragma unroll
    for (int mt = 0; mt < 2; ++mt)
#pragma unroll
        for (int nt = 0; nt < 8; ++nt) {
            const int n = wn + nt * 8 + tg * 2;
            const float bv0 = bias_s[n], bv1 = bias_s[n + 1];
#pragma unroll
            for (int h = 0; h < 2; ++h) {
                const int m = wm + mt * 16 + gid2 + h * 8;
                if (m0 + m < cnt) {
                    const int   t = toks_s[m];
                    const float w = wts_s[m];
                    float* op = out + (size_t)t * D_DIM + n0 + n;
                    atomicAdd(op,     (acc[mt][nt][2 * h + 0] + bv0) * w);
                    atomicAdd(op + 1, (acc[mt][nt][2 * h + 1] + bv1) * w);
                }
            }
        }
}

// ---------------- launch -----------------------------------------------------
extern "C" void kernel_launch(void* const* d_in, const int* in_sizes, int n_in,
                              void* d_out, int out_size) {
    const float* x  = (const float*)d_in[0];
    const float* gw = (const float*)d_in[1];
    const float* w1 = (const float*)d_in[2];
    const float* b1 = (const float*)d_in[3];
    const float* w2 = (const float*)d_in[4];
    const float* b2 = (const float*)d_in[5];
    float* out   = (float*)d_out;
    float* probs = out + (size_t)T_TOK * D_DIM;

    cudaFuncSetAttribute(k_fc1_h, cudaFuncAttributeMaxDynamicSharedMemorySize, SMEM_DYN);
    cudaFuncSetAttribute(k_fc2_h, cudaFuncAttributeMaxDynamicSharedMemorySize, SMEM_DYN);

    k_init<<<512, 256>>>((float4*)out);
    k_split<<<1024, 256>>>(x, w1, w2);
    k_gate<<<T_TOK / 8, 256>>>(x, gw, probs);
    k_prefix<<<1, 32>>>();
    k_fc1_h<<<dim3(F_DIM / 128, T_TOK / 128, E_EXP), 256, SMEM_DYN>>>(b1);
    k_fc2_h<<<dim3(D_DIM / 128, T_TOK / 128, E_EXP), 256, SMEM_DYN>>>(b2, out);
}